// round 1
// baseline (speedup 1.0000x reference)
#include <cuda_runtime.h>
#include <math.h>

#define H 4096
#define H3 (3 * H)
#define V 4
#define MS 104
#define MD 3
#define OUT 4

// scratch for h_bar (device globals are the allowed scratch mechanism)
__device__ float g_hbar[H];

__device__ __forceinline__ float sigmoidf_(float x) {
    return 1.0f / (1.0f + expf(-x));
}

// ---------------------------------------------------------------------------
// Kernel 1: h_bar[j] = w_sh[j,:] @ stack[0,:] + b_sh[j] + hidden0[j]
// ---------------------------------------------------------------------------
__global__ void k_hbar(const float* __restrict__ w_sh,
                       const float* __restrict__ b_sh,
                       const float* __restrict__ hidden0,
                       const float* __restrict__ stack) {
    int j = blockIdx.x * blockDim.x + threadIdx.x;
    if (j < H) {
        float s0 = stack[0], s1 = stack[1], s2 = stack[2];
        float v = fmaf(w_sh[j * 3 + 0], s0,
                  fmaf(w_sh[j * 3 + 1], s1,
                  fmaf(w_sh[j * 3 + 2], s2, b_sh[j] + hidden0[j])));
        g_hbar[j] = v;
    }
}

// ---------------------------------------------------------------------------
// Kernel 2: the heavy matvec + fused GRU gates.
// grid = H/4 blocks, 128 threads (4 warps). Warp w of block b owns hidden
// unit i = b*4 + w and computes gh rows i, i+H, i+2H plus gi, then h[i].
// h is written straight into d_out[4 + i].
// ---------------------------------------------------------------------------
__global__ void __launch_bounds__(128, 8)
k_gru(const float* __restrict__ w_hh,
      const float* __restrict__ w_ih,
      const float* __restrict__ b_ih,
      const float* __restrict__ b_hh,
      const float* __restrict__ emb,
      const int*   __restrict__ inp,
      float* __restrict__ out) {
    __shared__ float sh_hbar[H];
    __shared__ float sx[V];

    const int tid = threadIdx.x;

    // stage h_bar into shared (float4, coalesced): 1024 float4 / 128 threads
    const float4* hb4 = reinterpret_cast<const float4*>(g_hbar);
    float4* s4 = reinterpret_cast<float4*>(sh_hbar);
    #pragma unroll
    for (int j = tid; j < H / 4; j += 128) s4[j] = hb4[j];
    if (tid < V) sx[tid] = emb[inp[0] * V + tid];
    __syncthreads();

    const int warp = tid >> 5;
    const int lane = tid & 31;
    const int i = blockIdx.x * 4 + warp;   // hidden unit in [0, H)

    const float4* wr = reinterpret_cast<const float4*>(w_hh + (size_t)i        * H);
    const float4* wz = reinterpret_cast<const float4*>(w_hh + (size_t)(i + H)  * H);
    const float4* wn = reinterpret_cast<const float4*>(w_hh + (size_t)(i + 2*H)* H);

    float ar = 0.f, az = 0.f, an = 0.f;
    #pragma unroll 4
    for (int k = lane; k < H / 4; k += 32) {
        float4 h4 = s4[k];
        float4 r4 = wr[k];
        float4 z4 = wz[k];
        float4 n4 = wn[k];
        ar = fmaf(r4.x, h4.x, fmaf(r4.y, h4.y, fmaf(r4.z, h4.z, fmaf(r4.w, h4.w, ar))));
        az = fmaf(z4.x, h4.x, fmaf(z4.y, h4.y, fmaf(z4.z, h4.z, fmaf(z4.w, h4.w, az))));
        an = fmaf(n4.x, h4.x, fmaf(n4.y, h4.y, fmaf(n4.z, h4.z, fmaf(n4.w, h4.w, an))));
    }
    #pragma unroll
    for (int o = 16; o > 0; o >>= 1) {
        ar += __shfl_xor_sync(0xFFFFFFFFu, ar, o);
        az += __shfl_xor_sync(0xFFFFFFFFu, az, o);
        an += __shfl_xor_sync(0xFFFFFFFFu, an, o);
    }

    if (lane == 0) {
        // gi rows (tiny 4-element dots)
        const float x0 = sx[0], x1 = sx[1], x2 = sx[2], x3 = sx[3];
        const float* wir = w_ih + (size_t)i * V;
        const float* wiz = w_ih + (size_t)(i + H) * V;
        const float* win = w_ih + (size_t)(i + 2*H) * V;
        float gir = fmaf(wir[0], x0, fmaf(wir[1], x1, fmaf(wir[2], x2, fmaf(wir[3], x3, b_ih[i]))));
        float giz = fmaf(wiz[0], x0, fmaf(wiz[1], x1, fmaf(wiz[2], x2, fmaf(wiz[3], x3, b_ih[i + H]))));
        float gin = fmaf(win[0], x0, fmaf(win[1], x1, fmaf(win[2], x2, fmaf(win[3], x3, b_ih[i + 2*H]))));

        float ghr = ar + b_hh[i];
        float ghz = az + b_hh[i + H];
        float ghn = an + b_hh[i + 2*H];

        float r = sigmoidf_(gir + ghr);
        float z = sigmoidf_(giz + ghz);
        float n = tanhf(gin + r * ghn);
        float hb = sh_hbar[i];
        float h = (1.0f - z) * n + z * hb;
        out[OUT + i] = h;   // hidden region of d_out
    }
}

// ---------------------------------------------------------------------------
// Kernel 3: heads + stack update. One block, 288 threads (9 warps).
// Rows: 0-3 -> w_y, 4-5 -> w_a, 6-8 -> w_n. h lives in d_out[4 .. 4+H).
// ---------------------------------------------------------------------------
__global__ void k_heads(const float* __restrict__ w_y,
                        const float* __restrict__ b_y,
                        const float* __restrict__ w_n,
                        const float* __restrict__ b_n,
                        const float* __restrict__ w_a,
                        const float* __restrict__ b_a,
                        const float* __restrict__ stack,
                        float* __restrict__ out) {
    __shared__ float dots[9];
    __shared__ float a01[2];

    const float* h = out + OUT;
    const int warp = threadIdx.x >> 5;
    const int lane = threadIdx.x & 31;

    if (warp < 9) {
        const float* w;
        float b;
        if (warp < 4)      { w = w_y + (size_t)warp * H;        b = b_y[warp]; }
        else if (warp < 6) { w = w_a + (size_t)(warp - 4) * H;  b = b_a[warp - 4]; }
        else               { w = w_n + (size_t)(warp - 6) * H;  b = b_n[warp - 6]; }

        const float4* w4 = reinterpret_cast<const float4*>(w);
        const float4* h4 = reinterpret_cast<const float4*>(h);
        float acc = 0.f;
        #pragma unroll 4
        for (int k = lane; k < H / 4; k += 32) {
            float4 a = w4[k];
            float4 v = h4[k];
            acc = fmaf(a.x, v.x, fmaf(a.y, v.y, fmaf(a.z, v.z, fmaf(a.w, v.w, acc))));
        }
        #pragma unroll
        for (int o = 16; o > 0; o >>= 1) acc += __shfl_xor_sync(0xFFFFFFFFu, acc, o);
        if (lane == 0) dots[warp] = acc + b;
    }
    __syncthreads();

    if (threadIdx.x == 0) {
        // output = sigmoid(w_y @ h + b_y)
        out[0] = sigmoidf_(dots[0]);
        out[1] = sigmoidf_(dots[1]);
        out[2] = sigmoidf_(dots[2]);
        out[3] = sigmoidf_(dots[3]);
        // action = softmax(2 logits)
        float m  = fmaxf(dots[4], dots[5]);
        float e0 = expf(dots[4] - m);
        float e1 = expf(dots[5] - m);
        float inv = 1.0f / (e0 + e1);
        a01[0] = e0 * inv;
        a01[1] = e1 * inv;
    }
    __syncthreads();

    const float a0 = a01[0];
    const float a1 = a01[1];
    // new_stack[r][m] = a0 * push[r][m] + a1 * pop[r][m]
    for (int idx = threadIdx.x; idx < MS * MD; idx += blockDim.x) {
        int r = idx / MD;
        int m = idx - r * MD;
        float push = (r == 0)      ? sigmoidf_(dots[6 + m]) : stack[(r - 1) * MD + m];
        float pop  = (r == MS - 1) ? 0.0f                   : stack[(r + 1) * MD + m];
        out[OUT + H + idx] = fmaf(a0, push, a1 * pop);
    }
}

// ---------------------------------------------------------------------------
// Launch. Input order (metadata): inp, hidden0, stack, emb, w_ih, w_hh,
// b_ih, b_hh, w_y, b_y, w_n, b_n, w_a, b_a, w_sh, b_sh.
// Output: [output(4) | hidden(4096) | new_stack(312)] f32.
// ---------------------------------------------------------------------------
extern "C" void kernel_launch(void* const* d_in, const int* in_sizes, int n_in,
                              void* d_out, int out_size) {
    const int*   inp     = (const int*)  d_in[0];
    const float* hidden0 = (const float*)d_in[1];
    const float* stack   = (const float*)d_in[2];
    const float* emb     = (const float*)d_in[3];
    const float* w_ih    = (const float*)d_in[4];
    const float* w_hh    = (const float*)d_in[5];
    const float* b_ih    = (const float*)d_in[6];
    const float* b_hh    = (const float*)d_in[7];
    const float* w_y     = (const float*)d_in[8];
    const float* b_y     = (const float*)d_in[9];
    const float* w_n     = (const float*)d_in[10];
    const float* b_n     = (const float*)d_in[11];
    const float* w_a     = (const float*)d_in[12];
    const float* b_a     = (const float*)d_in[13];
    const float* w_sh    = (const float*)d_in[14];
    const float* b_sh    = (const float*)d_in[15];
    float* out = (float*)d_out;

    k_hbar<<<H / 128, 128>>>(w_sh, b_sh, hidden0, stack);
    k_gru<<<H / 4, 128>>>(w_hh, w_ih, b_ih, b_hh, emb, inp, out);
    k_heads<<<1, 288>>>(w_y, b_y, w_n, b_n, w_a, b_a, stack, out);
}

// round 2
// speedup vs baseline: 1.2178x; 1.2178x over previous
#include <cuda_runtime.h>
#include <math.h>

#define H 4096
#define V 4
#define MS 104
#define MD 3
#define OUT 4
#define GRID_GRU 1024   // H/4 blocks, 4 warps each, 1 hidden unit per warp

// scratch (device globals are the allowed scratch mechanism)
__device__ float g_hbar[H];
__device__ float g_dots[9];            // zero-init at load; finale resets -> clean each replay
__device__ unsigned int g_count = 0;   // last-block detector; finale resets

__device__ __forceinline__ float sigmoidf_(float x) {
    return 1.0f / (1.0f + expf(-x));
}

// ---------------------------------------------------------------------------
// Kernel 1: h_bar = w_sh @ stack[0] + b_sh + hidden0   (fully float4-vectorized)
// 1024 threads, thread t owns hidden units 4t..4t+3.
// w_sh is (H,3): rows 4t..4t+3 occupy floats [12t, 12t+12) = float4 idx 3t..3t+2.
// ---------------------------------------------------------------------------
__global__ void k_hbar(const float* __restrict__ w_sh,
                       const float* __restrict__ b_sh,
                       const float* __restrict__ hidden0,
                       const float* __restrict__ stack) {
    int t = blockIdx.x * blockDim.x + threadIdx.x;   // 0..1023
    const float4* w4  = reinterpret_cast<const float4*>(w_sh);
    const float4* b4p = reinterpret_cast<const float4*>(b_sh);
    const float4* h4p = reinterpret_cast<const float4*>(hidden0);

    float s0 = stack[0], s1 = stack[1], s2 = stack[2];
    float4 a = w4[3 * t + 0];
    float4 b = w4[3 * t + 1];
    float4 c = w4[3 * t + 2];
    float4 bb = b4p[t];
    float4 h0 = h4p[t];

    float4 r;
    r.x = fmaf(a.x, s0, fmaf(a.y, s1, fmaf(a.z, s2, bb.x + h0.x)));
    r.y = fmaf(a.w, s0, fmaf(b.x, s1, fmaf(b.y, s2, bb.y + h0.y)));
    r.z = fmaf(b.z, s0, fmaf(b.w, s1, fmaf(c.x, s2, bb.z + h0.z)));
    r.w = fmaf(c.y, s0, fmaf(c.z, s1, fmaf(c.w, s2, bb.w + h0.w)));
    reinterpret_cast<float4*>(g_hbar)[t] = r;
}

// ---------------------------------------------------------------------------
// Kernel 2: heavy matvec + GRU gates + fused heads + last-block finale.
// grid = 1024 blocks x 128 threads. Warp w of block b owns hidden unit
// i = b*4 + w: computes gh rows i, i+H, i+2H, the gi dot, gate math, h[i].
// Then the block contributes w_y/w_a/w_n partial dots via atomicAdd and the
// last block to finish performs sigmoid/softmax/stack-update.
// ---------------------------------------------------------------------------
__global__ void __launch_bounds__(128, 8)
k_gru(const float* __restrict__ w_hh,
      const float* __restrict__ w_ih,
      const float* __restrict__ b_ih,
      const float* __restrict__ b_hh,
      const float* __restrict__ emb,
      const int*   __restrict__ inp,
      const float* __restrict__ w_y,
      const float* __restrict__ b_y,
      const float* __restrict__ w_n,
      const float* __restrict__ b_n,
      const float* __restrict__ w_a,
      const float* __restrict__ b_a,
      const float* __restrict__ stack,
      float* __restrict__ out) {
    __shared__ float sh_hbar[H];
    __shared__ float sx[V];
    __shared__ float sh_h[4];         // h value per warp
    __shared__ float sh_fin[12];      // [0..8]=dots+bias, [9]=a0, [10]=a1, [11]=is_last flag

    const int tid = threadIdx.x;

    // stage h_bar into shared (coalesced float4)
    const float4* hb4 = reinterpret_cast<const float4*>(g_hbar);
    float4* s4 = reinterpret_cast<float4*>(sh_hbar);
    #pragma unroll
    for (int j = tid; j < H / 4; j += 128) s4[j] = hb4[j];
    if (tid < V) sx[tid] = emb[inp[0] * V + tid];
    if (tid == 0) sh_fin[11] = 0.0f;
    __syncthreads();

    const int warp = tid >> 5;
    const int lane = tid & 31;
    const int i = blockIdx.x * 4 + warp;   // hidden unit

    const float4* wr = reinterpret_cast<const float4*>(w_hh + (size_t)i          * H);
    const float4* wz = reinterpret_cast<const float4*>(w_hh + (size_t)(i + H)    * H);
    const float4* wn = reinterpret_cast<const float4*>(w_hh + (size_t)(i + 2*H)  * H);

    float ar = 0.f, az = 0.f, an = 0.f;
    #pragma unroll 4
    for (int k = lane; k < H / 4; k += 32) {
        float4 h4 = s4[k];
        float4 r4 = __ldcs(wr + k);   // read-once streams: evict-first
        float4 z4 = __ldcs(wz + k);
        float4 n4 = __ldcs(wn + k);
        ar = fmaf(r4.x, h4.x, fmaf(r4.y, h4.y, fmaf(r4.z, h4.z, fmaf(r4.w, h4.w, ar))));
        az = fmaf(z4.x, h4.x, fmaf(z4.y, h4.y, fmaf(z4.z, h4.z, fmaf(z4.w, h4.w, az))));
        an = fmaf(n4.x, h4.x, fmaf(n4.y, h4.y, fmaf(n4.z, h4.z, fmaf(n4.w, h4.w, an))));
    }
    #pragma unroll
    for (int o = 16; o > 0; o >>= 1) {
        ar += __shfl_xor_sync(0xFFFFFFFFu, ar, o);
        az += __shfl_xor_sync(0xFFFFFFFFu, az, o);
        an += __shfl_xor_sync(0xFFFFFFFFu, an, o);
    }

    if (lane == 0) {
        const float x0 = sx[0], x1 = sx[1], x2 = sx[2], x3 = sx[3];
        const float* wir = w_ih + (size_t)i * V;
        const float* wiz = w_ih + (size_t)(i + H) * V;
        const float* win = w_ih + (size_t)(i + 2*H) * V;
        float gir = fmaf(wir[0], x0, fmaf(wir[1], x1, fmaf(wir[2], x2, fmaf(wir[3], x3, b_ih[i]))));
        float giz = fmaf(wiz[0], x0, fmaf(wiz[1], x1, fmaf(wiz[2], x2, fmaf(wiz[3], x3, b_ih[i + H]))));
        float gin = fmaf(win[0], x0, fmaf(win[1], x1, fmaf(win[2], x2, fmaf(win[3], x3, b_ih[i + 2*H]))));

        float r = sigmoidf_(gir + ar + b_hh[i]);
        float z = sigmoidf_(giz + az + b_hh[i + H]);
        float n = tanhf(gin + (an + b_hh[i + 2*H]) * r);
        float hb = sh_hbar[i];
        float h = (1.0f - z) * n + z * hb;
        out[OUT + i] = h;
        sh_h[warp] = h;
    }
    __syncthreads();

    // head contributions: threads 0..8, one head each, rows i0..i0+3 are one float4
    if (tid < 9) {
        const int i0 = blockIdx.x * 4;
        const float* w = (tid < 4) ? (w_y + (size_t)tid * H)
                       : (tid < 6) ? (w_a + (size_t)(tid - 4) * H)
                                   : (w_n + (size_t)(tid - 6) * H);
        float4 wv = *reinterpret_cast<const float4*>(w + i0);
        float acc = fmaf(wv.x, sh_h[0], fmaf(wv.y, sh_h[1],
                    fmaf(wv.z, sh_h[2], wv.w * sh_h[3])));
        atomicAdd(&g_dots[tid], acc);
    }

    // last-block detection
    if (tid == 0) {
        __threadfence();
        unsigned int old = atomicAdd(&g_count, 1u);
        if (old == GRID_GRU - 1) sh_fin[11] = 1.0f;
    }
    __syncthreads();
    if (sh_fin[11] == 0.0f) return;

    // ---- finale (last block only): heads + softmax + stack update ----
    if (tid < 9) {
        float d = atomicExch(&g_dots[tid], 0.0f);     // read + reset for next replay
        float bias = (tid < 4) ? b_y[tid] : (tid < 6) ? b_a[tid - 4] : b_n[tid - 6];
        sh_fin[tid] = d + bias;
    }
    if (tid == 32) atomicExch(&g_count, 0u);          // reset detector
    __syncthreads();

    if (tid == 0) {
        out[0] = sigmoidf_(sh_fin[0]);
        out[1] = sigmoidf_(sh_fin[1]);
        out[2] = sigmoidf_(sh_fin[2]);
        out[3] = sigmoidf_(sh_fin[3]);
        float m  = fmaxf(sh_fin[4], sh_fin[5]);
        float e0 = expf(sh_fin[4] - m);
        float e1 = expf(sh_fin[5] - m);
        float inv = 1.0f / (e0 + e1);
        sh_fin[9]  = e0 * inv;
        sh_fin[10] = e1 * inv;
    }
    __syncthreads();

    const float a0 = sh_fin[9];
    const float a1 = sh_fin[10];
    for (int idx = tid; idx < MS * MD; idx += 128) {
        int r = idx / MD;
        int m = idx - r * MD;
        float push = (r == 0)      ? sigmoidf_(sh_fin[6 + m]) : stack[(r - 1) * MD + m];
        float pop  = (r == MS - 1) ? 0.0f                     : stack[(r + 1) * MD + m];
        out[OUT + H + idx] = fmaf(a0, push, a1 * pop);
    }
}

// ---------------------------------------------------------------------------
// Launch. Input order: inp, hidden0, stack, emb, w_ih, w_hh, b_ih, b_hh,
// w_y, b_y, w_n, b_n, w_a, b_a, w_sh, b_sh.
// Output: [output(4) | hidden(4096) | new_stack(312)] f32.
// ---------------------------------------------------------------------------
extern "C" void kernel_launch(void* const* d_in, const int* in_sizes, int n_in,
                              void* d_out, int out_size) {
    const int*   inp     = (const int*)  d_in[0];
    const float* hidden0 = (const float*)d_in[1];
    const float* stack   = (const float*)d_in[2];
    const float* emb     = (const float*)d_in[3];
    const float* w_ih    = (const float*)d_in[4];
    const float* w_hh    = (const float*)d_in[5];
    const float* b_ih    = (const float*)d_in[6];
    const float* b_hh    = (const float*)d_in[7];
    const float* w_y     = (const float*)d_in[8];
    const float* b_y     = (const float*)d_in[9];
    const float* w_n     = (const float*)d_in[10];
    const float* b_n     = (const float*)d_in[11];
    const float* w_a     = (const float*)d_in[12];
    const float* b_a     = (const float*)d_in[13];
    const float* w_sh    = (const float*)d_in[14];
    const float* b_sh    = (const float*)d_in[15];
    float* out = (float*)d_out;

    k_hbar<<<4, 256>>>(w_sh, b_sh, hidden0, stack);
    k_gru<<<GRID_GRU, 128>>>(w_hh, w_ih, b_ih, b_hh, emb, inp,
                             w_y, b_y, w_n, b_n, w_a, b_a, stack, out);
}